// round 16
// baseline (speedup 1.0000x reference)
#include <cuda_runtime.h>
#include <cuda_bf16.h>
#include <math.h>
#include <cstdint>

#define BATCH 8192
#define DIM   128
#define NSUPER 528               // 32*33/2 supertiles of 256x256
#define GRID_MAIN 148
#define THREADS 512

#define MARGIN_F 0.1f
#define ONE_M_EPS 0.99999f
#define LOG2E 1.44269504089f
// arg = scale*(sim-0.5)*log2e -> sim*A + B
#define A_POS (-2.0f * LOG2E)
#define B_POS (LOG2E)
#define A_NEG (40.0f * LOG2E)
#define B_NEG (-20.0f * LOG2E)

__device__ __nv_bfloat16 g_fb[BATCH * DIM];
__device__ unsigned int g_min_enc[BATCH];
__device__ unsigned int g_max_enc[BATCH];
__device__ float g_possum[BATCH];
__device__ float g_negsum[BATCH];
__device__ unsigned int g_done;

__device__ __forceinline__ float inf_f() { return __int_as_float(0x7f800000); }
__device__ __forceinline__ unsigned enc_f(float x) {
    unsigned u = __float_as_uint(x);
    return (u & 0x80000000u) ? ~u : (u | 0x80000000u);
}
__device__ __forceinline__ float dec_f(unsigned e) {
    return __uint_as_float((e & 0x80000000u) ? (e & 0x7FFFFFFFu) : ~e);
}
__device__ __forceinline__ float ex2f(float x) {
    float r;
    asm("ex2.approx.f32 %0, %1;" : "=f"(r) : "f"(x));
    return r;
}
__device__ __forceinline__ uint32_t smem_to_u32(const void* p) {
    uint32_t a;
    asm("{ .reg .u64 t; cvta.to.shared.u64 t, %1; cvt.u32.u64 %0, t; }"
        : "=r"(a) : "l"(p));
    return a;
}
__device__ __forceinline__ void ldsm_x4(uint32_t (&r)[4], uint32_t addr) {
    asm volatile("ldmatrix.sync.aligned.m8n8.x4.shared.b16 {%0,%1,%2,%3}, [%4];"
                 : "=r"(r[0]), "=r"(r[1]), "=r"(r[2]), "=r"(r[3]) : "r"(addr));
}
__device__ __forceinline__ void mma_bf16(float (&d)[4], const uint32_t (&a)[4],
                                         uint32_t b0, uint32_t b1) {
    asm volatile("mma.sync.aligned.m16n8k16.row.col.f32.bf16.bf16.f32 "
                 "{%0,%1,%2,%3}, {%4,%5,%6,%7}, {%8,%9}, {%0,%1,%2,%3};"
                 : "+f"(d[0]), "+f"(d[1]), "+f"(d[2]), "+f"(d[3])
                 : "r"(a[0]), "r"(a[1]), "r"(a[2]), "r"(a[3]), "r"(b0), "r"(b1));
}
#define CP_ASYNC16(sa, g) \
    asm volatile("cp.async.cg.shared.global [%0], [%1], 16;" :: "r"(sa), "l"(g) : "memory")
#define CP_COMMIT() asm volatile("cp.async.commit_group;" ::: "memory")
#define CP_WAIT0()  asm volatile("cp.async.wait_group 0;" ::: "memory")

// ---- smem layout (bytes) ----
#define OFF_A    0           // 2 panels x 32KB
#define OFF_B    65536       // 2 panels x 32KB
#define OFF_LABA 131072      // int[256]
#define OFF_LABB 132096      // int[256]
#define OFF_TPR  133120      // float[256] each
#define OFF_TNR  134144
#define OFF_TPC  135168
#define OFF_TNC  136192
#define OFF_RR0  137216      // float[2][4][128] each (4KB)
#define OFF_RR1  141312
#define OFF_RC0  145408      // float[2][128]-style per-q panels
#define OFF_RC1  149504
#define SMEM_BYTES 153600

__device__ __forceinline__ void decode_st(int k, int& ti, int& tj) {
    int a = (int)((sqrtf(8.0f * (float)k + 1.0f) - 1.0f) * 0.5f);
    while ((a + 1) * (a + 2) / 2 <= k) ++a;
    while (a * (a + 1) / 2 > k) --a;
    tj = a;
    ti = k - a * (a + 1) / 2;   // ti <= tj
}

// prefetch one 256x256 supertile (B skipped when I==J)
__device__ __forceinline__ void prefetch_super(int I, int J, uint32_t sb,
                                               const int* L, int tid) {
    const char* srcA = (const char*)(g_fb + (size_t)I * 256 * DIM);
#pragma unroll
    for (int i = 0; i < 8; i++) {
        int idx = tid + i * THREADS;   // 0..4095
        int r = idx >> 4, c = idx & 15;
        CP_ASYNC16(sb + OFF_A + r * 256 + ((c ^ (r & 7)) << 4), srcA + r * 256 + c * 16);
    }
    if (I != J) {
        const char* srcB = (const char*)(g_fb + (size_t)J * 256 * DIM);
#pragma unroll
        for (int i = 0; i < 8; i++) {
            int idx = tid + i * THREADS;
            int r = idx >> 4, c = idx & 15;
            CP_ASYNC16(sb + OFF_B + r * 256 + ((c ^ (r & 7)) << 4), srcB + r * 256 + c * 16);
        }
    }
    if (tid < 64)
        CP_ASYNC16(sb + OFF_LABA + tid * 16, L + I * 256 + tid * 4);
    else if (tid < 128 && I != J)
        CP_ASYNC16(sb + OFF_LABB + (tid - 64) * 16, L + J * 256 + (tid - 64) * 4);
}

__global__ void prep_k(const float* __restrict__ F, float* __restrict__ out) {
    int idx = blockIdx.x * blockDim.x + threadIdx.x;   // 262144
    float4 v = ((const float4*)F)[idx];
    ((__nv_bfloat162*)g_fb)[idx * 2]     = __floats2bfloat162_rn(v.x, v.y);
    ((__nv_bfloat162*)g_fb)[idx * 2 + 1] = __floats2bfloat162_rn(v.z, v.w);
    if (idx < BATCH) {
        g_min_enc[idx] = 0xFFFFFFFFu;
        g_max_enc[idx] = 0u;
        g_possum[idx] = 0.0f;
        g_negsum[idx] = 0.0f;
    }
    if (idx == 0) { g_done = 0u; out[0] = 0.0f; }
}

// one 128x128 subtile GEMM, warp computes 32x32
__device__ __forceinline__ void gemm_sub(uint32_t aBase, uint32_t bBase,
                                         const uint32_t (&aRow)[2], const uint32_t (&aSw)[2],
                                         const uint32_t (&bRow)[2], const uint32_t (&bSw)[2],
                                         int khA, int khB, float (&d)[2][4][4]) {
#pragma unroll
    for (int mt = 0; mt < 2; mt++)
#pragma unroll
        for (int nt = 0; nt < 4; nt++)
#pragma unroll
            for (int r = 0; r < 4; r++) d[mt][nt][r] = 0.0f;
#pragma unroll
    for (int ks = 0; ks < 8; ks++) {
        uint32_t a[2][4], bb[2][4];
#pragma unroll
        for (int mt = 0; mt < 2; mt++)
            ldsm_x4(a[mt], aBase + aRow[mt] + (((2 * ks + khA) ^ aSw[mt]) << 4));
#pragma unroll
        for (int p = 0; p < 2; p++)
            ldsm_x4(bb[p], bBase + bRow[p] + (((2 * ks + khB) ^ bSw[p]) << 4));
#pragma unroll
        for (int mt = 0; mt < 2; mt++)
#pragma unroll
            for (int nt = 0; nt < 4; nt++)
                mma_bf16(d[mt][nt], a[mt], bb[nt >> 1][(nt & 1) * 2],
                         bb[nt >> 1][(nt & 1) * 2 + 1]);
    }
}

// epilogue over one warp's 32x32 fragment; DIAG subtiles skip col stats
template <int PASS, bool DIAG>
__device__ __forceinline__ void epi_frag(
    const float (&d)[2][4][4], const int* labR, const int* labC,
    const int (&rowL)[4], const int (&colL)[8],
    const float* tpr, const float* tnr, const float* tpc, const float* tnc,
    float (&s0r)[4], float (&s1r)[4], float (&s0c)[8], float (&s1c)[8]) {
    int rl[4], cl[8];
#pragma unroll
    for (int i = 0; i < 4; i++) rl[i] = labR[rowL[i]];
#pragma unroll
    for (int j = 0; j < 8; j++) cl[j] = labC[colL[j]];
    float pR[4], nR[4], pC[8], nC[8];
    if (PASS == 1) {
#pragma unroll
        for (int i = 0; i < 4; i++) { pR[i] = tpr[rowL[i]]; nR[i] = tnr[rowL[i]]; }
        if (!DIAG)
#pragma unroll
            for (int j = 0; j < 8; j++) { pC[j] = tpc[colL[j]]; nC[j] = tnc[colL[j]]; }
    }
#pragma unroll
    for (int mt = 0; mt < 2; mt++)
#pragma unroll
        for (int nt = 0; nt < 4; nt++)
#pragma unroll
            for (int rix = 0; rix < 4; rix++) {
                const int i = mt * 2 + (rix >> 1);
                const int cj = nt * 2 + (rix & 1);
                const float sim = d[mt][nt][rix];
                const bool same = (rl[i] == cl[cj]);
                const bool self = DIAG && (rowL[i] == colL[cj]);
                if (PASS == 0) {
                    if (same) {
                        if (sim < ONE_M_EPS && !self) {
                            s0r[i] = fminf(s0r[i], sim);
                            if (!DIAG) s0c[cj] = fminf(s0c[cj], sim);
                        }
                    } else {
                        s1r[i] = fmaxf(s1r[i], sim);
                        if (!DIAG) s1c[cj] = fmaxf(s1c[cj], sim);
                    }
                } else {
                    const float e = ex2f(fmaf(sim, same ? A_POS : A_NEG,
                                              same ? B_POS : B_NEG));
                    if (same) {
                        if (!self) {
                            if (sim < pR[i]) s0r[i] += e;
                            if (!DIAG && sim < pC[cj]) s0c[cj] += e;
                        }
                    } else {
                        if (sim > nR[i]) s1r[i] += e;
                        if (!DIAG && sim > nC[cj]) s1c[cj] += e;
                    }
                }
            }
}

template <int PASS>
__device__ __forceinline__ void col_reduce(float (&s0c)[8], float (&s1c)[8],
                                           float* rc0, float* rc1,
                                           const int (&colL)[8], int wm, int lane) {
#pragma unroll
    for (int cj = 0; cj < 8; cj++) {
        float v0 = s0c[cj], v1 = s1c[cj];
#pragma unroll
        for (int m = 4; m <= 16; m <<= 1) {
            float o0 = __shfl_xor_sync(0xffffffff, v0, m);
            float o1 = __shfl_xor_sync(0xffffffff, v1, m);
            if (PASS == 0) { v0 = fminf(v0, o0); v1 = fmaxf(v1, o1); }
            else           { v0 += o0; v1 += o1; }
        }
        if (lane < 4) {
            rc0[wm * 128 + colL[cj]] = v0;
            rc1[wm * 128 + colL[cj]] = v1;
        }
    }
}

template <int PASS>
__global__ __launch_bounds__(THREADS, 1)
void ms_tri(const int* __restrict__ L, float* __restrict__ out) {
    extern __shared__ char smem[];
    const uint32_t sb = smem_to_u32(smem);
    const int tid = threadIdx.x;
    const int lane = tid & 31;
    const int w = tid >> 5;
    const int wm = w >> 2, wn = w & 3;   // 4x4 warp grid, 32x32 warp tile

    uint32_t aRow[2], aSw[2], bRow[2], bSw[2];
    const int khA = lane >> 4;
    const int khB = (lane >> 3) & 1;
#pragma unroll
    for (int mt = 0; mt < 2; mt++) {
        int r = wm * 32 + mt * 16 + (lane & 15);
        aRow[mt] = r * 256;
        aSw[mt] = r & 7;
    }
#pragma unroll
    for (int p = 0; p < 2; p++) {
        int r = wn * 32 + p * 16 + ((lane >> 4) << 3) + (lane & 7);
        bRow[p] = r * 256;
        bSw[p] = r & 7;
    }
    int rowL[4], colL[8];
#pragma unroll
    for (int i = 0; i < 4; i++)
        rowL[i] = wm * 32 + (i >> 1) * 16 + (lane >> 2) + (i & 1) * 8;
#pragma unroll
    for (int cj = 0; cj < 8; cj++)
        colL[cj] = wn * 32 + (cj >> 1) * 8 + 2 * (lane & 3) + (cj & 1);

    const float* tpr = (const float*)(smem + OFF_TPR);
    const float* tnr = (const float*)(smem + OFF_TNR);
    const float* tpc = (const float*)(smem + OFF_TPC);
    const float* tnc = (const float*)(smem + OFF_TNC);
    const int* labA = (const int*)(smem + OFF_LABA);
    const int* labB = (const int*)(smem + OFF_LABB);
    float* rr0 = (float*)(smem + OFF_RR0);
    float* rr1 = (float*)(smem + OFF_RR1);
    float* rc0 = (float*)(smem + OFF_RC0);
    float* rc1 = (float*)(smem + OFF_RC1);

    {
        int I, J;
        decode_st(blockIdx.x, I, J);
        prefetch_super(I, J, sb, L, tid);
    }
    CP_COMMIT();

    for (int st = blockIdx.x; st < NSUPER; st += GRID_MAIN) {
        int I, J;
        decode_st(st, I, J);
        const bool diagS = (I == J);
        const uint32_t aB = sb + OFF_A;
        const uint32_t bB = diagS ? (sb + OFF_A) : (sb + OFF_B);
        const int* labC = diagS ? labA : labB;

        CP_WAIT0();
        __syncthreads();   // tile data + labels visible; rr/rc free

        if (PASS == 1) {   // per-supertile thresholds (cols loaded even when diag)
            if (tid < 256) {
                float mn = dec_f(g_min_enc[I * 256 + tid]);
                float mx = dec_f(g_max_enc[I * 256 + tid]);
                ((float*)(smem + OFF_TPR))[tid] = fminf(ONE_M_EPS, mx + MARGIN_F);
                ((float*)(smem + OFF_TNR))[tid] = mn - MARGIN_F;
            } else {
                int c = tid - 256;
                float mn = dec_f(g_min_enc[J * 256 + c]);
                float mx = dec_f(g_max_enc[J * 256 + c]);
                ((float*)(smem + OFF_TPC))[c] = fminf(ONE_M_EPS, mx + MARGIN_F);
                ((float*)(smem + OFF_TNC))[c] = mn - MARGIN_F;
            }
            __syncthreads();
        }

        // row stats persist across whole supertile; col stats per q-panel
        float s0r[2][4], s1r[2][4];
#pragma unroll
        for (int p = 0; p < 2; p++)
#pragma unroll
            for (int i = 0; i < 4; i++) {
                s0r[p][i] = (PASS == 0) ? inf_f() : 0.0f;
                s1r[p][i] = (PASS == 0) ? -inf_f() : 0.0f;
            }

        float d[2][4][4];
        // ----- q = 0 -----
        {
            float s0c[8], s1c[8];
#pragma unroll
            for (int j = 0; j < 8; j++) {
                s0c[j] = (PASS == 0) ? inf_f() : 0.0f;
                s1c[j] = (PASS == 0) ? -inf_f() : 0.0f;
            }
            // (p=0, q=0)
            gemm_sub(aB, bB, aRow, aSw, bRow, bSw, khA, khB, d);
            if (diagS)
                epi_frag<PASS, true>(d, labA, labC, rowL, colL,
                                     tpr, tnr, tpc, tnc, s0r[0], s1r[0], s0c, s1c);
            else
                epi_frag<PASS, false>(d, labA, labC, rowL, colL,
                                      tpr, tnr, tpc, tnc, s0r[0], s1r[0], s0c, s1c);
            // (p=1, q=0): skip if diag supertile (lower subtile)
            if (!diagS) {
                gemm_sub(aB + 32768, bB, aRow, aSw, bRow, bSw, khA, khB, d);
                epi_frag<PASS, false>(d, labA + 128, labC, rowL, colL,
                                      tpr + 128, tnr + 128, tpc, tnc,
                                      s0r[1], s1r[1], s0c, s1c);
            }
            col_reduce<PASS>(s0c, s1c, rc0, rc1, colL, wm, lane);
        }
        // ----- q = 1 -----
        {
            float s0c[8], s1c[8];
#pragma unroll
            for (int j = 0; j < 8; j++) {
                s0c[j] = (PASS == 0) ? inf_f() : 0.0f;
                s1c[j] = (PASS == 0) ? -inf_f() : 0.0f;
            }
            // (p=0, q=1): always off-diagonal
            gemm_sub(aB, bB + 32768, aRow, aSw, bRow, bSw, khA, khB, d);
            epi_frag<PASS, false>(d, labA, labC + 128, rowL, colL,
                                  tpr, tnr, tpc + 128, tnc + 128,
                                  s0r[0], s1r[0], s0c, s1c);
            // (p=1, q=1)
            gemm_sub(aB + 32768, bB + 32768, aRow, aSw, bRow, bSw, khA, khB, d);
            if (diagS)
                epi_frag<PASS, true>(d, labA + 128, labC + 128, rowL, colL,
                                     tpr + 128, tnr + 128, tpc + 128, tnc + 128,
                                     s0r[1], s1r[1], s0c, s1c);
            else
                epi_frag<PASS, false>(d, labA + 128, labC + 128, rowL, colL,
                                      tpr + 128, tnr + 128, tpc + 128, tnc + 128,
                                      s0r[1], s1r[1], s0c, s1c);
            col_reduce<PASS>(s0c, s1c, rc0 + 512, rc1 + 512, colL, wm, lane);
        }

        // row shfl reduce -> rr
#pragma unroll
        for (int p = 0; p < 2; p++)
#pragma unroll
            for (int i = 0; i < 4; i++) {
                float v0 = s0r[p][i], v1 = s1r[p][i];
#pragma unroll
                for (int m = 1; m <= 2; m <<= 1) {
                    float o0 = __shfl_xor_sync(0xffffffff, v0, m);
                    float o1 = __shfl_xor_sync(0xffffffff, v1, m);
                    if (PASS == 0) { v0 = fminf(v0, o0); v1 = fmaxf(v1, o1); }
                    else           { v0 += o0; v1 += o1; }
                }
                if ((lane & 3) == 0) {
                    rr0[p * 512 + wn * 128 + rowL[i]] = v0;
                    rr1[p * 512 + wn * 128 + rowL[i]] = v1;
                }
            }
        __syncthreads();   // reductions written; all warps done reading tiles

        if (st + GRID_MAIN < NSUPER) {   // overlap next loads with atomics
            int I2, J2;
            decode_st(st + GRID_MAIN, I2, J2);
            prefetch_super(I2, J2, sb, L, tid);
        }
        CP_COMMIT();

        if (tid < 256) {   // rows
            int p = tid >> 7, r = tid & 127;
            const float* b0 = rr0 + p * 512 + r;
            const float* b1 = rr1 + p * 512 + r;
            if (PASS == 0) {
                float mn = fminf(fminf(b0[0], b0[128]), fminf(b0[256], b0[384]));
                float mx = fmaxf(fmaxf(b1[0], b1[128]), fmaxf(b1[256], b1[384]));
                atomicMin(&g_min_enc[I * 256 + tid], enc_f(mn));
                atomicMax(&g_max_enc[I * 256 + tid], enc_f(mx));
            } else {
                atomicAdd(&g_possum[I * 256 + tid], b0[0] + b0[128] + b0[256] + b0[384]);
                atomicAdd(&g_negsum[I * 256 + tid], b1[0] + b1[128] + b1[256] + b1[384]);
            }
        } else {           // cols (diag-subtile entries are identity no-ops)
            int c = tid - 256;
            int q = c >> 7, cl = c & 127;
            const float* b0 = rc0 + q * 512 + cl;
            const float* b1 = rc1 + q * 512 + cl;
            if (PASS == 0) {
                float mn = fminf(fminf(b0[0], b0[128]), fminf(b0[256], b0[384]));
                float mx = fmaxf(fmaxf(b1[0], b1[128]), fmaxf(b1[256], b1[384]));
                atomicMin(&g_min_enc[J * 256 + c], enc_f(mn));
                atomicMax(&g_max_enc[J * 256 + c], enc_f(mx));
            } else {
                atomicAdd(&g_possum[J * 256 + c], b0[0] + b0[128] + b0[256] + b0[384]);
                atomicAdd(&g_negsum[J * 256 + c], b1[0] + b1[128] + b1[256] + b1[384]);
            }
        }
    }

    // ----- pass 1: fused finalize (last CTA) -----
    if (PASS == 1) {
        __shared__ unsigned rank;
        __threadfence();
        __syncthreads();
        if (tid == 0) rank = atomicAdd(&g_done, 1u);
        __syncthreads();
        if (rank == GRID_MAIN - 1) {
            __threadfence();
            float local = 0.0f;
            for (int r = tid; r < BATCH; r += THREADS) {
                float mn = dec_f(g_min_enc[r]);
                float mx = dec_f(g_max_enc[r]);
                if (mn < inf_f() && mx > -inf_f() && (mn - MARGIN_F < mx))
                    local += 0.5f * log1pf(g_possum[r]) + 0.025f * log1pf(g_negsum[r]);
            }
#pragma unroll
            for (int m = 16; m > 0; m >>= 1)
                local += __shfl_xor_sync(0xffffffff, local, m);
            float* red = (float*)(smem + OFF_RR0);
            if (lane == 0) red[w] = local;
            __syncthreads();
            if (tid == 0) {
                float tot = 0.0f;
#pragma unroll
                for (int i = 0; i < 16; i++) tot += red[i];
                out[0] = tot;
            }
        }
    }
}

extern "C" void kernel_launch(void* const* d_in, const int* in_sizes, int n_in,
                              void* d_out, int out_size) {
    const float* F = (const float*)d_in[0];
    const int* L = (const int*)d_in[1];
    if (n_in >= 2 && in_sizes[0] == BATCH) {  // defensive: inputs swapped
        F = (const float*)d_in[1];
        L = (const int*)d_in[0];
    }

    cudaFuncSetAttribute(ms_tri<0>, cudaFuncAttributeMaxDynamicSharedMemorySize, SMEM_BYTES);
    cudaFuncSetAttribute(ms_tri<1>, cudaFuncAttributeMaxDynamicSharedMemorySize, SMEM_BYTES);

    prep_k<<<1024, 256>>>(F, (float*)d_out);
    ms_tri<0><<<GRID_MAIN, THREADS, SMEM_BYTES>>>(L, (float*)d_out);
    ms_tri<1><<<GRID_MAIN, THREADS, SMEM_BYTES>>>(L, (float*)d_out);
}

// round 17
// speedup vs baseline: 1.0041x; 1.0041x over previous
#include <cuda_runtime.h>
#include <cuda_bf16.h>
#include <math.h>
#include <cstdint>

#define BATCH 8192
#define DIM   128
#define NSUPER 528               // 32*33/2 supertiles of 256x256
#define GRID_MAIN 148
#define THREADS 512

#define MARGIN_F 0.1f
#define ONE_M_EPS 0.99999f
#define LOG2E 1.44269504089f
// arg = scale*(sim-0.5)*log2e -> sim*A + B
#define A_POS (-2.0f * LOG2E)
#define B_POS (LOG2E)
#define A_NEG (40.0f * LOG2E)
#define B_NEG (-20.0f * LOG2E)

__device__ __nv_bfloat16 g_fb[BATCH * DIM];
__device__ unsigned int g_min_enc[BATCH];
__device__ unsigned int g_max_enc[BATCH];
__device__ float g_possum[BATCH];
__device__ float g_negsum[BATCH];
__device__ unsigned int g_done;

__device__ __forceinline__ float inf_f() { return __int_as_float(0x7f800000); }
__device__ __forceinline__ unsigned enc_f(float x) {
    unsigned u = __float_as_uint(x);
    return (u & 0x80000000u) ? ~u : (u | 0x80000000u);
}
__device__ __forceinline__ float dec_f(unsigned e) {
    return __uint_as_float((e & 0x80000000u) ? (e & 0x7FFFFFFFu) : ~e);
}
__device__ __forceinline__ float ex2f(float x) {
    float r;
    asm("ex2.approx.f32 %0, %1;" : "=f"(r) : "f"(x));
    return r;
}
__device__ __forceinline__ uint32_t smem_to_u32(const void* p) {
    uint32_t a;
    asm("{ .reg .u64 t; cvta.to.shared.u64 t, %1; cvt.u32.u64 %0, t; }"
        : "=r"(a) : "l"(p));
    return a;
}
__device__ __forceinline__ void ldsm_x4(uint32_t (&r)[4], uint32_t addr) {
    asm volatile("ldmatrix.sync.aligned.m8n8.x4.shared.b16 {%0,%1,%2,%3}, [%4];"
                 : "=r"(r[0]), "=r"(r[1]), "=r"(r[2]), "=r"(r[3]) : "r"(addr));
}
__device__ __forceinline__ void mma_bf16(float (&d)[4], const uint32_t (&a)[4],
                                         uint32_t b0, uint32_t b1) {
    asm volatile("mma.sync.aligned.m16n8k16.row.col.f32.bf16.bf16.f32 "
                 "{%0,%1,%2,%3}, {%4,%5,%6,%7}, {%8,%9}, {%0,%1,%2,%3};"
                 : "+f"(d[0]), "+f"(d[1]), "+f"(d[2]), "+f"(d[3])
                 : "r"(a[0]), "r"(a[1]), "r"(a[2]), "r"(a[3]), "r"(b0), "r"(b1));
}
#define CP_ASYNC16(sa, g) \
    asm volatile("cp.async.cg.shared.global [%0], [%1], 16;" :: "r"(sa), "l"(g) : "memory")
#define CP_COMMIT() asm volatile("cp.async.commit_group;" ::: "memory")
#define CP_WAIT0()  asm volatile("cp.async.wait_group 0;" ::: "memory")

// ---- smem layout (bytes) ----
#define OFF_A    0           // 2 panels x 32KB
#define OFF_B    65536       // 2 panels x 32KB
#define OFF_LABA 131072      // int[256]
#define OFF_LABB 132096      // int[256]
#define OFF_TPR  133120      // float[256] each
#define OFF_TNR  134144
#define OFF_TPC  135168
#define OFF_TNC  136192
#define OFF_RR0  137216      // float[2][4][128] each (4KB)
#define OFF_RR1  141312
#define OFF_RC0  145408      // float[2][128]-style per-q panels
#define OFF_RC1  149504
#define SMEM_BYTES 153600

__device__ __forceinline__ void decode_st(int k, int& ti, int& tj) {
    int a = (int)((sqrtf(8.0f * (float)k + 1.0f) - 1.0f) * 0.5f);
    while ((a + 1) * (a + 2) / 2 <= k) ++a;
    while (a * (a + 1) / 2 > k) --a;
    tj = a;
    ti = k - a * (a + 1) / 2;   // ti <= tj
}

// prefetch one 256x256 supertile (B skipped when I==J)
__device__ __forceinline__ void prefetch_super(int I, int J, uint32_t sb,
                                               const int* L, int tid) {
    const char* srcA = (const char*)(g_fb + (size_t)I * 256 * DIM);
#pragma unroll
    for (int i = 0; i < 8; i++) {
        int idx = tid + i * THREADS;   // 0..4095
        int r = idx >> 4, c = idx & 15;
        CP_ASYNC16(sb + OFF_A + r * 256 + ((c ^ (r & 7)) << 4), srcA + r * 256 + c * 16);
    }
    if (I != J) {
        const char* srcB = (const char*)(g_fb + (size_t)J * 256 * DIM);
#pragma unroll
        for (int i = 0; i < 8; i++) {
            int idx = tid + i * THREADS;
            int r = idx >> 4, c = idx & 15;
            CP_ASYNC16(sb + OFF_B + r * 256 + ((c ^ (r & 7)) << 4), srcB + r * 256 + c * 16);
        }
    }
    if (tid < 64)
        CP_ASYNC16(sb + OFF_LABA + tid * 16, L + I * 256 + tid * 4);
    else if (tid < 128 && I != J)
        CP_ASYNC16(sb + OFF_LABB + (tid - 64) * 16, L + J * 256 + (tid - 64) * 4);
}

__global__ void prep_k(const float* __restrict__ F, float* __restrict__ out) {
    int idx = blockIdx.x * blockDim.x + threadIdx.x;   // 262144
    float4 v = ((const float4*)F)[idx];
    ((__nv_bfloat162*)g_fb)[idx * 2]     = __floats2bfloat162_rn(v.x, v.y);
    ((__nv_bfloat162*)g_fb)[idx * 2 + 1] = __floats2bfloat162_rn(v.z, v.w);
    if (idx < BATCH) {
        g_min_enc[idx] = 0xFFFFFFFFu;
        g_max_enc[idx] = 0u;
        g_possum[idx] = 0.0f;
        g_negsum[idx] = 0.0f;
    }
    if (idx == 0) { g_done = 0u; out[0] = 0.0f; }
}

// one 128x128 subtile GEMM, warp computes 32x32
__device__ __forceinline__ void gemm_sub(uint32_t aBase, uint32_t bBase,
                                         const uint32_t (&aRow)[2], const uint32_t (&aSw)[2],
                                         const uint32_t (&bRow)[2], const uint32_t (&bSw)[2],
                                         int khA, int khB, float (&d)[2][4][4]) {
#pragma unroll
    for (int mt = 0; mt < 2; mt++)
#pragma unroll
        for (int nt = 0; nt < 4; nt++)
#pragma unroll
            for (int r = 0; r < 4; r++) d[mt][nt][r] = 0.0f;
#pragma unroll
    for (int ks = 0; ks < 8; ks++) {
        uint32_t a[2][4], bb[2][4];
#pragma unroll
        for (int mt = 0; mt < 2; mt++)
            ldsm_x4(a[mt], aBase + aRow[mt] + (((2 * ks + khA) ^ aSw[mt]) << 4));
#pragma unroll
        for (int p = 0; p < 2; p++)
            ldsm_x4(bb[p], bBase + bRow[p] + (((2 * ks + khB) ^ bSw[p]) << 4));
#pragma unroll
        for (int mt = 0; mt < 2; mt++)
#pragma unroll
            for (int nt = 0; nt < 4; nt++)
                mma_bf16(d[mt][nt], a[mt], bb[nt >> 1][(nt & 1) * 2],
                         bb[nt >> 1][(nt & 1) * 2 + 1]);
    }
}

// epilogue over one warp's 32x32 fragment; DIAG subtiles skip col stats
template <int PASS, bool DIAG>
__device__ __forceinline__ void epi_frag(
    const float (&d)[2][4][4], const int* labR, const int* labC,
    const int (&rowL)[4], const int (&colL)[8],
    const float* tpr, const float* tnr, const float* tpc, const float* tnc,
    float (&s0r)[4], float (&s1r)[4], float (&s0c)[8], float (&s1c)[8]) {
    int rl[4], cl[8];
#pragma unroll
    for (int i = 0; i < 4; i++) rl[i] = labR[rowL[i]];
#pragma unroll
    for (int j = 0; j < 8; j++) cl[j] = labC[colL[j]];
    float pR[4], nR[4], pC[8], nC[8];
    if (PASS == 1) {
#pragma unroll
        for (int i = 0; i < 4; i++) { pR[i] = tpr[rowL[i]]; nR[i] = tnr[rowL[i]]; }
        if (!DIAG)
#pragma unroll
            for (int j = 0; j < 8; j++) { pC[j] = tpc[colL[j]]; nC[j] = tnc[colL[j]]; }
    }
#pragma unroll
    for (int mt = 0; mt < 2; mt++)
#pragma unroll
        for (int nt = 0; nt < 4; nt++)
#pragma unroll
            for (int rix = 0; rix < 4; rix++) {
                const int i = mt * 2 + (rix >> 1);
                const int cj = nt * 2 + (rix & 1);
                const float sim = d[mt][nt][rix];
                const bool same = (rl[i] == cl[cj]);
                const bool self = DIAG && (rowL[i] == colL[cj]);
                if (PASS == 0) {
                    if (same) {
                        if (sim < ONE_M_EPS && !self) {
                            s0r[i] = fminf(s0r[i], sim);
                            if (!DIAG) s0c[cj] = fminf(s0c[cj], sim);
                        }
                    } else {
                        s1r[i] = fmaxf(s1r[i], sim);
                        if (!DIAG) s1c[cj] = fmaxf(s1c[cj], sim);
                    }
                } else {
                    const float e = ex2f(fmaf(sim, same ? A_POS : A_NEG,
                                              same ? B_POS : B_NEG));
                    if (same) {
                        if (!self) {
                            if (sim < pR[i]) s0r[i] += e;
                            if (!DIAG && sim < pC[cj]) s0c[cj] += e;
                        }
                    } else {
                        if (sim > nR[i]) s1r[i] += e;
                        if (!DIAG && sim > nC[cj]) s1c[cj] += e;
                    }
                }
            }
}

template <int PASS>
__device__ __forceinline__ void col_reduce(float (&s0c)[8], float (&s1c)[8],
                                           float* rc0, float* rc1,
                                           const int (&colL)[8], int wm, int lane) {
#pragma unroll
    for (int cj = 0; cj < 8; cj++) {
        float v0 = s0c[cj], v1 = s1c[cj];
#pragma unroll
        for (int m = 4; m <= 16; m <<= 1) {
            float o0 = __shfl_xor_sync(0xffffffff, v0, m);
            float o1 = __shfl_xor_sync(0xffffffff, v1, m);
            if (PASS == 0) { v0 = fminf(v0, o0); v1 = fmaxf(v1, o1); }
            else           { v0 += o0; v1 += o1; }
        }
        if (lane < 4) {
            rc0[wm * 128 + colL[cj]] = v0;
            rc1[wm * 128 + colL[cj]] = v1;
        }
    }
}

template <int PASS>
__global__ __launch_bounds__(THREADS, 1)
void ms_tri(const int* __restrict__ L, float* __restrict__ out) {
    extern __shared__ char smem[];
    const uint32_t sb = smem_to_u32(smem);
    const int tid = threadIdx.x;
    const int lane = tid & 31;
    const int w = tid >> 5;
    const int wm = w >> 2, wn = w & 3;   // 4x4 warp grid, 32x32 warp tile

    uint32_t aRow[2], aSw[2], bRow[2], bSw[2];
    const int khA = lane >> 4;
    const int khB = (lane >> 3) & 1;
#pragma unroll
    for (int mt = 0; mt < 2; mt++) {
        int r = wm * 32 + mt * 16 + (lane & 15);
        aRow[mt] = r * 256;
        aSw[mt] = r & 7;
    }
#pragma unroll
    for (int p = 0; p < 2; p++) {
        int r = wn * 32 + p * 16 + ((lane >> 4) << 3) + (lane & 7);
        bRow[p] = r * 256;
        bSw[p] = r & 7;
    }
    int rowL[4], colL[8];
#pragma unroll
    for (int i = 0; i < 4; i++)
        rowL[i] = wm * 32 + (i >> 1) * 16 + (lane >> 2) + (i & 1) * 8;
#pragma unroll
    for (int cj = 0; cj < 8; cj++)
        colL[cj] = wn * 32 + (cj >> 1) * 8 + 2 * (lane & 3) + (cj & 1);

    const float* tpr = (const float*)(smem + OFF_TPR);
    const float* tnr = (const float*)(smem + OFF_TNR);
    const float* tpc = (const float*)(smem + OFF_TPC);
    const float* tnc = (const float*)(smem + OFF_TNC);
    const int* labA = (const int*)(smem + OFF_LABA);
    const int* labB = (const int*)(smem + OFF_LABB);
    float* rr0 = (float*)(smem + OFF_RR0);
    float* rr1 = (float*)(smem + OFF_RR1);
    float* rc0 = (float*)(smem + OFF_RC0);
    float* rc1 = (float*)(smem + OFF_RC1);

    {
        int I, J;
        decode_st(blockIdx.x, I, J);
        prefetch_super(I, J, sb, L, tid);
    }
    CP_COMMIT();

    for (int st = blockIdx.x; st < NSUPER; st += GRID_MAIN) {
        int I, J;
        decode_st(st, I, J);
        const bool diagS = (I == J);
        const uint32_t aB = sb + OFF_A;
        const uint32_t bB = diagS ? (sb + OFF_A) : (sb + OFF_B);
        const int* labC = diagS ? labA : labB;

        CP_WAIT0();
        __syncthreads();   // tile data + labels visible; rr/rc free

        if (PASS == 1) {   // per-supertile thresholds (cols loaded even when diag)
            if (tid < 256) {
                float mn = dec_f(g_min_enc[I * 256 + tid]);
                float mx = dec_f(g_max_enc[I * 256 + tid]);
                ((float*)(smem + OFF_TPR))[tid] = fminf(ONE_M_EPS, mx + MARGIN_F);
                ((float*)(smem + OFF_TNR))[tid] = mn - MARGIN_F;
            } else {
                int c = tid - 256;
                float mn = dec_f(g_min_enc[J * 256 + c]);
                float mx = dec_f(g_max_enc[J * 256 + c]);
                ((float*)(smem + OFF_TPC))[c] = fminf(ONE_M_EPS, mx + MARGIN_F);
                ((float*)(smem + OFF_TNC))[c] = mn - MARGIN_F;
            }
            __syncthreads();
        }

        // row stats persist across whole supertile; col stats per q-panel
        float s0r[2][4], s1r[2][4];
#pragma unroll
        for (int p = 0; p < 2; p++)
#pragma unroll
            for (int i = 0; i < 4; i++) {
                s0r[p][i] = (PASS == 0) ? inf_f() : 0.0f;
                s1r[p][i] = (PASS == 0) ? -inf_f() : 0.0f;
            }

        float d[2][4][4];
        // ----- q = 0 -----
        {
            float s0c[8], s1c[8];
#pragma unroll
            for (int j = 0; j < 8; j++) {
                s0c[j] = (PASS == 0) ? inf_f() : 0.0f;
                s1c[j] = (PASS == 0) ? -inf_f() : 0.0f;
            }
            // (p=0, q=0)
            gemm_sub(aB, bB, aRow, aSw, bRow, bSw, khA, khB, d);
            if (diagS)
                epi_frag<PASS, true>(d, labA, labC, rowL, colL,
                                     tpr, tnr, tpc, tnc, s0r[0], s1r[0], s0c, s1c);
            else
                epi_frag<PASS, false>(d, labA, labC, rowL, colL,
                                      tpr, tnr, tpc, tnc, s0r[0], s1r[0], s0c, s1c);
            // (p=1, q=0): skip if diag supertile (lower subtile)
            if (!diagS) {
                gemm_sub(aB + 32768, bB, aRow, aSw, bRow, bSw, khA, khB, d);
                epi_frag<PASS, false>(d, labA + 128, labC, rowL, colL,
                                      tpr + 128, tnr + 128, tpc, tnc,
                                      s0r[1], s1r[1], s0c, s1c);
            }
            col_reduce<PASS>(s0c, s1c, rc0, rc1, colL, wm, lane);
        }
        // ----- q = 1 -----
        {
            float s0c[8], s1c[8];
#pragma unroll
            for (int j = 0; j < 8; j++) {
                s0c[j] = (PASS == 0) ? inf_f() : 0.0f;
                s1c[j] = (PASS == 0) ? -inf_f() : 0.0f;
            }
            // (p=0, q=1): always off-diagonal
            gemm_sub(aB, bB + 32768, aRow, aSw, bRow, bSw, khA, khB, d);
            epi_frag<PASS, false>(d, labA, labC + 128, rowL, colL,
                                  tpr, tnr, tpc + 128, tnc + 128,
                                  s0r[0], s1r[0], s0c, s1c);
            // (p=1, q=1)
            gemm_sub(aB + 32768, bB + 32768, aRow, aSw, bRow, bSw, khA, khB, d);
            if (diagS)
                epi_frag<PASS, true>(d, labA + 128, labC + 128, rowL, colL,
                                     tpr + 128, tnr + 128, tpc + 128, tnc + 128,
                                     s0r[1], s1r[1], s0c, s1c);
            else
                epi_frag<PASS, false>(d, labA + 128, labC + 128, rowL, colL,
                                      tpr + 128, tnr + 128, tpc + 128, tnc + 128,
                                      s0r[1], s1r[1], s0c, s1c);
            col_reduce<PASS>(s0c, s1c, rc0 + 512, rc1 + 512, colL, wm, lane);
        }

        // row shfl reduce -> rr
#pragma unroll
        for (int p = 0; p < 2; p++)
#pragma unroll
            for (int i = 0; i < 4; i++) {
                float v0 = s0r[p][i], v1 = s1r[p][i];
#pragma unroll
                for (int m = 1; m <= 2; m <<= 1) {
                    float o0 = __shfl_xor_sync(0xffffffff, v0, m);
                    float o1 = __shfl_xor_sync(0xffffffff, v1, m);
                    if (PASS == 0) { v0 = fminf(v0, o0); v1 = fmaxf(v1, o1); }
                    else           { v0 += o0; v1 += o1; }
                }
                if ((lane & 3) == 0) {
                    rr0[p * 512 + wn * 128 + rowL[i]] = v0;
                    rr1[p * 512 + wn * 128 + rowL[i]] = v1;
                }
            }
        __syncthreads();   // reductions written; all warps done reading tiles

        if (st + GRID_MAIN < NSUPER) {   // overlap next loads with atomics
            int I2, J2;
            decode_st(st + GRID_MAIN, I2, J2);
            prefetch_super(I2, J2, sb, L, tid);
        }
        CP_COMMIT();

        if (tid < 256) {   // rows
            int p = tid >> 7, r = tid & 127;
            const float* b0 = rr0 + p * 512 + r;
            const float* b1 = rr1 + p * 512 + r;
            if (PASS == 0) {
                float mn = fminf(fminf(b0[0], b0[128]), fminf(b0[256], b0[384]));
                float mx = fmaxf(fmaxf(b1[0], b1[128]), fmaxf(b1[256], b1[384]));
                atomicMin(&g_min_enc[I * 256 + tid], enc_f(mn));
                atomicMax(&g_max_enc[I * 256 + tid], enc_f(mx));
            } else {
                atomicAdd(&g_possum[I * 256 + tid], b0[0] + b0[128] + b0[256] + b0[384]);
                atomicAdd(&g_negsum[I * 256 + tid], b1[0] + b1[128] + b1[256] + b1[384]);
            }
        } else {           // cols (diag-subtile entries are identity no-ops)
            int c = tid - 256;
            int q = c >> 7, cl = c & 127;
            const float* b0 = rc0 + q * 512 + cl;
            const float* b1 = rc1 + q * 512 + cl;
            if (PASS == 0) {
                float mn = fminf(fminf(b0[0], b0[128]), fminf(b0[256], b0[384]));
                float mx = fmaxf(fmaxf(b1[0], b1[128]), fmaxf(b1[256], b1[384]));
                atomicMin(&g_min_enc[J * 256 + c], enc_f(mn));
                atomicMax(&g_max_enc[J * 256 + c], enc_f(mx));
            } else {
                atomicAdd(&g_possum[J * 256 + c], b0[0] + b0[128] + b0[256] + b0[384]);
                atomicAdd(&g_negsum[J * 256 + c], b1[0] + b1[128] + b1[256] + b1[384]);
            }
        }
    }

    // ----- pass 1: fused finalize (last CTA) -----
    if (PASS == 1) {
        __shared__ unsigned rank;
        __threadfence();
        __syncthreads();
        if (tid == 0) rank = atomicAdd(&g_done, 1u);
        __syncthreads();
        if (rank == GRID_MAIN - 1) {
            __threadfence();
            float local = 0.0f;
            for (int r = tid; r < BATCH; r += THREADS) {
                float mn = dec_f(g_min_enc[r]);
                float mx = dec_f(g_max_enc[r]);
                if (mn < inf_f() && mx > -inf_f() && (mn - MARGIN_F < mx))
                    local += 0.5f * log1pf(g_possum[r]) + 0.025f * log1pf(g_negsum[r]);
            }
#pragma unroll
            for (int m = 16; m > 0; m >>= 1)
                local += __shfl_xor_sync(0xffffffff, local, m);
            float* red = (float*)(smem + OFF_RR0);
            if (lane == 0) red[w] = local;
            __syncthreads();
            if (tid == 0) {
                float tot = 0.0f;
#pragma unroll
                for (int i = 0; i < 16; i++) tot += red[i];
                out[0] = tot;
            }
        }
    }
}

extern "C" void kernel_launch(void* const* d_in, const int* in_sizes, int n_in,
                              void* d_out, int out_size) {
    const float* F = (const float*)d_in[0];
    const int* L = (const int*)d_in[1];
    if (n_in >= 2 && in_sizes[0] == BATCH) {  // defensive: inputs swapped
        F = (const float*)d_in[1];
        L = (const int*)d_in[0];
    }

    cudaFuncSetAttribute(ms_tri<0>, cudaFuncAttributeMaxDynamicSharedMemorySize, SMEM_BYTES);
    cudaFuncSetAttribute(ms_tri<1>, cudaFuncAttributeMaxDynamicSharedMemorySize, SMEM_BYTES);

    prep_k<<<1024, 256>>>(F, (float*)d_out);
    ms_tri<0><<<GRID_MAIN, THREADS, SMEM_BYTES>>>(L, (float*)d_out);
    ms_tri<1><<<GRID_MAIN, THREADS, SMEM_BYTES>>>(L, (float*)d_out);
}